// round 8
// baseline (speedup 1.0000x reference)
#include <cuda_runtime.h>
#include <math.h>

typedef unsigned long long u64;

#define NB 64
#define NC 64
#define NT 512
#define NV 25
#define NK 3
#define NO 64

// -------- scratch (device globals) --------
__device__ float g_Y[(size_t)NB * NO * NT * NV];   // GCN output after BN+hswish
__device__ float g_An[NK * NV * 32];               // A_norm, padded w-stride 32 (zeros in pad)

__device__ __forceinline__ float hswish(float x) {
    return x * fminf(fmaxf(x + 3.0f, 0.0f), 6.0f) * (1.0f / 6.0f);
}
__device__ __forceinline__ u64 ffma2(u64 a, u64 b, u64 c) {
    u64 d; asm("fma.rn.f32x2 %0, %1, %2, %3;" : "=l"(d) : "l"(a), "l"(b), "l"(c)); return d;
}
__device__ __forceinline__ u64 dup2(float v) {
    u64 d; asm("mov.b64 %0, {%1, %1};" : "=l"(d) : "f"(v)); return d;
}
__device__ __forceinline__ void unpk(u64 p, float& lo, float& hi) {
    asm("mov.b64 {%0, %1}, %2;" : "=f"(lo), "=f"(hi) : "l"(p));
}

// ===================== K0: adjacency normalization (unchanged from passing R2) =====================
__global__ void prep_kernel(const float* __restrict__ Af, const float* __restrict__ Al) {
    __shared__ float dsh[NK * NV];
    int tid = threadIdx.x;
    if (tid < NK * NV) {
        int base = tid * NV;
        float s = 0.0f;
        #pragma unroll
        for (int w = 0; w < NV; w++) s += fabsf(Af[base + w] + Al[base + w]);
        dsh[tid] = rsqrtf(fmaxf(s, 1e-6f));
    }
    __syncthreads();
    for (int i = tid; i < NK * NV * 32; i += blockDim.x) {
        int row = i >> 5;          // k*25+v
        int w = i & 31;
        float val = 0.0f;
        if (w < NV) {
            int k = row / NV;
            int src = row * NV + w;
            float a = fabsf(Af[src] + Al[src]);
            val = dsh[row] * a * dsh[k * NV + w];
        }
        g_An[i] = val;
    }
}

// ===================== K1: GCN =====================
// grid (T/4, B), 256 threads, 2 blocks/SM. Same geometry as the passing R2 kernel;
// inner loops rebuilt with row-paired f32x2 (weights transposed in smem, stride 68).
// smem floats: Xs[64*100] @0 6400, Uk[64*100] @6400 6400,
//              Wt[3][64][68] @12800 13056, An[3*25*32] @25856 2400 -> 28256 fl = 113,024 B
#define GC_UK 6400
#define GC_WT 12800
#define GC_AN 25856
#define GC_TOT 28256

__global__ void __launch_bounds__(256, 2)
gcn_kernel(const float* __restrict__ x, const float* __restrict__ Wg,
           const float* __restrict__ gscale, const float* __restrict__ gbias) {
    extern __shared__ float sm[];
    float* Xs = sm;
    float* Uk = sm + GC_UK;
    float* Wt = sm + GC_WT;
    float* An = sm + GC_AN;

    int tid = threadIdx.x;
    int t0 = blockIdx.x * 4;
    int b = blockIdx.y;

    // ---- cooperative loads ----
    {
        const float4* xsrc = (const float4*)(x + ((size_t)b * NC * NT + t0) * NV);
        for (int i = tid; i < 1600; i += 256) {
            int c = i / 25, q = i - c * 25;
            ((float4*)Xs)[i] = xsrc[c * 3200 + q];
        }
        // Wt[k][c][o] = Wg[k][o][c]
        for (int i = tid; i < NK * NO * NC; i += 256) {
            int k = i >> 12, o = (i >> 6) & 63, c = i & 63;
            Wt[k * 4352 + c * 68 + o] = Wg[i];
        }
        const float4* asrc = (const float4*)g_An;
        for (int i = tid; i < 600; i += 256) ((float4*)An)[i] = asrc[i];
    }
    __syncthreads();

    int rg = tid >> 7;                 // 0..1 -> rows rg*32 .. rg*32+31 (16 pairs)
    int p = tid & 127;                 // 0..127
    bool pok = p < 100;
    int pc = pok ? p : 99;             // clamped: all smem reads stay in-array
    int o_ = tid >> 2, tt_ = tid & 3;

    u64 bacc[14];
    #pragma unroll
    for (int q = 0; q < 14; q++) bacc[q] = 0ull;

    for (int k = 0; k < NK; k++) {
        // ---- stage A: U[j][p] = sum_c W[k][j][c]*X[c][p], row-paired ----
        u64 acc[16];
        #pragma unroll
        for (int i = 0; i < 16; i++) acc[i] = 0ull;
        const float* Wk = Wt + k * 4352 + rg * 32;
        #pragma unroll 4
        for (int c = 0; c < NC; c++) {
            u64 xd = dup2(Xs[c * 100 + pc]);
            const ulonglong2* wrow = (const ulonglong2*)(Wk + c * 68);
            #pragma unroll
            for (int i = 0; i < 8; i++) {
                ulonglong2 ww = wrow[i];
                acc[2 * i]     = ffma2(xd, ww.x, acc[2 * i]);
                acc[2 * i + 1] = ffma2(xd, ww.y, acc[2 * i + 1]);
            }
        }
        if (pok) {
            #pragma unroll
            for (int i = 0; i < 16; i++) {
                float lo, hi; unpk(acc[i], lo, hi);
                Uk[(rg * 32 + 2 * i) * 100 + p] = lo;
                Uk[(rg * 32 + 2 * i + 1) * 100 + p] = hi;
            }
        }
        __syncthreads();

        // ---- stage B: bacc[w-pairs] += U[o][tt*25+v] * An[k][v][:] ----
        {
            const float* Ur = Uk + o_ * 100 + tt_ * 25;
            const float* Ar = An + k * 800;
            #pragma unroll 5
            for (int v = 0; v < NV; v++) {
                u64 uv = dup2(Ur[v]);
                const ulonglong2* A2 = (const ulonglong2*)(Ar + v * 32);
                #pragma unroll
                for (int q = 0; q < 7; q++) {
                    ulonglong2 aa = A2[q];
                    bacc[2 * q]     = ffma2(uv, aa.x, bacc[2 * q]);
                    bacc[2 * q + 1] = ffma2(uv, aa.y, bacc[2 * q + 1]);
                }
            }
        }
        __syncthreads();
    }

    // ---- epilogue: BN + hswish -> stage into Uk -> coalesced float4 store ----
    {
        float s = gscale[o_] * (1.0f / 3.0f);
        float bi = gbias[o_];
        float* yrow = Uk + o_ * 100 + tt_ * 25;
        #pragma unroll
        for (int j = 0; j < 13; j++) {
            float lo, hi; unpk(bacc[j], lo, hi);
            yrow[2 * j] = hswish(lo * s + bi);
            if (2 * j + 1 < NV) yrow[2 * j + 1] = hswish(hi * s + bi);
        }
    }
    __syncthreads();
    {
        float4* ydst = (float4*)(g_Y + ((size_t)b * NO * NT + t0) * NV);
        for (int i = tid; i < 1600; i += 256) {
            int oo = i / 25, q = i - oo * 25;
            ydst[oo * 3200 + q] = ((const float4*)Uk)[i];
        }
    }
}

// ===================== K2: TCN =====================
// grid (T/4, B), 256 threads. Depthwise reads g_Y through L1 (no smem stage).
// smem floats: T1[64*100] @0 6400, Pwt[64][68] @6400 4352, Dw[64*12] @10752 768,
//              PR[256] @11520 -> 11776 fl = 47,104 B
#define TC_PW 6400
#define TC_DW 10752
#define TC_PR 11520
#define TC_TOT 11776

__global__ void __launch_bounds__(256, 2)
tcn_kernel(const float* __restrict__ x, const float* __restrict__ dwg,
           const float* __restrict__ pwg, const float* __restrict__ s1g,
           const float* __restrict__ b1g, const float* __restrict__ s2g,
           const float* __restrict__ b2g, float* __restrict__ out) {
    extern __shared__ float sm[];
    float* T1 = sm;
    float* Pwt = sm + TC_PW;
    float* Dw = sm + TC_DW;
    float* PR = sm + TC_PR;

    int tid = threadIdx.x;
    int t0 = blockIdx.x * 4;
    int b = blockIdx.y;

    // ---- param loads ----
    for (int i = tid; i < NO * NC; i += 256) {
        int o = i >> 6, c = i & 63;
        Pwt[c * 68 + o] = pwg[i];          // transposed, row-pairs contiguous
    }
    for (int i = tid; i < NO * 9; i += 256) {
        int c = i / 9, j = i - c * 9;
        Dw[c * 12 + j] = dwg[i];
    }
    if (tid < 64) {
        PR[tid] = s1g[tid]; PR[64 + tid] = b1g[tid];
        PR[128 + tid] = s2g[tid]; PR[192 + tid] = b2g[tid];
    }
    __syncthreads();

    // ---- depthwise k=9 + BN1 + hswish -> T1 ----
    const float* Yb = g_Y + ((size_t)b * NO * NT + t0) * NV;
    bool interior = (t0 >= 4) && (t0 <= NT - 8);
    for (int i = tid; i < 6400; i += 256) {
        int c = i / 100, p = i - c * 100;
        const float* yp = Yb + c * (NT * NV) + p - 100;   // tap j=0 -> t-4
        const float* dr = Dw + c * 12;
        float a = 0.0f;
        if (interior) {
            #pragma unroll
            for (int j = 0; j < 9; j++) a = fmaf(__ldg(yp + j * 25), dr[j], a);
        } else {
            int tloc = t0 + p / 25;
            #pragma unroll
            for (int j = 0; j < 9; j++) {
                int tg = tloc - 4 + j;
                if (tg >= 0 && tg < NT) a = fmaf(__ldg(yp + j * 25), dr[j], a);
            }
        }
        T1[i] = hswish(a * PR[c] + PR[64 + c]);
    }
    __syncthreads();

    // ---- pointwise 64x64 (row-paired f32x2) + BN2 + residual + hswish ----
    int rg = tid >> 7;                  // rows rg*32 .. rg*32+31
    int p = tid & 127;
    bool pok = p < 100;
    int pc = pok ? p : 99;

    u64 acc[16];
    #pragma unroll
    for (int i = 0; i < 16; i++) acc[i] = 0ull;

    #pragma unroll 4
    for (int c = 0; c < NC; c++) {
        u64 td = dup2(T1[c * 100 + pc]);
        const ulonglong2* wrow = (const ulonglong2*)(Pwt + c * 68 + rg * 32);
        #pragma unroll
        for (int i = 0; i < 8; i++) {
            ulonglong2 ww = wrow[i];
            acc[2 * i]     = ffma2(td, ww.x, acc[2 * i]);
            acc[2 * i + 1] = ffma2(td, ww.y, acc[2 * i + 1]);
        }
    }

    if (pok) {
        size_t ob = ((size_t)b * NC * NT + t0) * NV + p;
        #pragma unroll
        for (int i = 0; i < 16; i++) {
            int o0 = rg * 32 + 2 * i;
            float lo, hi; unpk(acc[i], lo, hi);
            size_t a0 = ob + (size_t)o0 * (NT * NV);
            size_t a1 = a0 + (size_t)(NT * NV);
            float v0 = lo * PR[128 + o0] + PR[192 + o0] + __ldg(x + a0);
            float v1 = hi * PR[128 + o0 + 1] + PR[192 + o0 + 1] + __ldg(x + a1);
            out[a0] = hswish(v0);
            out[a1] = hswish(v1);
        }
    }
}

// ===================== launcher =====================
extern "C" void kernel_launch(void* const* d_in, const int* in_sizes, int n_in,
                              void* d_out, int out_size) {
    const float* x  = (const float*)d_in[0];
    const float* Af = (const float*)d_in[1];
    const float* Al = (const float*)d_in[2];
    const float* Wg = (const float*)d_in[3];
    const float* gs = (const float*)d_in[4];
    const float* gb = (const float*)d_in[5];
    const float* dw = (const float*)d_in[6];
    const float* pw = (const float*)d_in[7];
    const float* s1 = (const float*)d_in[8];
    const float* b1 = (const float*)d_in[9];
    const float* s2 = (const float*)d_in[10];
    const float* b2 = (const float*)d_in[11];
    float* out = (float*)d_out;

    (void)in_sizes; (void)n_in; (void)out_size;

    cudaFuncSetAttribute(gcn_kernel, cudaFuncAttributeMaxDynamicSharedMemorySize,
                         GC_TOT * (int)sizeof(float));
    cudaFuncSetAttribute(tcn_kernel, cudaFuncAttributeMaxDynamicSharedMemorySize,
                         TC_TOT * (int)sizeof(float));

    prep_kernel<<<1, 128>>>(Af, Al);
    gcn_kernel<<<dim3(NT / 4, NB), 256, GC_TOT * sizeof(float)>>>(x, Wg, gs, gb);
    tcn_kernel<<<dim3(NT / 4, NB), 256, TC_TOT * sizeof(float)>>>(x, dw, pw, s1, b1, s2, b2, out);
}